// round 12
// baseline (speedup 1.0000x reference)
#include <cuda_runtime.h>
#include <cstdint>

#define NCLS   10
#define NB     32
#define NBINS  (NB * NCLS)      // 320
#define NAT    512
#define DIN    272
#define HID    64
#define NOUT   128
#define L0OUT  256
#define IN0    32
#define ATILE  64
#define NT     256
#define PADA   68               // s1 row stride (floats): 16B-multiple (LDS.128 safe)

__device__ __forceinline__ float silu_f(float x) {
    return x * (1.0f / (1.0f + __expf(-x)));
}

// packed dual-fp32 FMA: d.lo += a.lo*b.lo ; d.hi += a.hi*b.hi
__device__ __forceinline__ void ffma2(unsigned long long& d,
                                      unsigned long long a,
                                      unsigned long long b) {
    asm("fma.rn.f32x2 %0, %1, %2, %0;" : "+l"(d) : "l"(a), "l"(b));
}
__device__ __forceinline__ float lo32(unsigned long long v) {
    return __uint_as_float((unsigned)(v & 0xffffffffull));
}
__device__ __forceinline__ float hi32(unsigned long long v) {
    return __uint_as_float((unsigned)(v >> 32));
}

// ===========================================================================
// Single fused kernel: block = (b, cls). Locally compacts its batch's atoms,
// runs the 2-stage MLP on 64-atom tiles (a-paired FFMA2, dup'd weights),
// reduces s2 over atoms, applies Wout, writes its own 128 outputs.
// No global scratch, no multi-kernel lifecycle.
// ===========================================================================
__global__ __launch_bounds__(NT, 3) void fused_kernel(
    const float* __restrict__ af,      // (16384, 272)
    const float* __restrict__ W0,      // (T, 32, 256)
    const float* __restrict__ W1,      // (T, 64, 256)
    const float* __restrict__ Wo,      // (T, 64, 128)
    const int*   __restrict__ mapping, // (16384)
    float*       __restrict__ out)     // (NB, T*128)
{
    __shared__ float WaD[IN0 * 2 * HID];   // [k][(o,o) dup] 16KB
    __shared__ float WbD[HID * 2 * HID];   // [k][(o,o) dup] 32KB
    __shared__ float xs[IN0 * ATILE];      // [k][a]          8KB
    __shared__ float s1[HID * PADA];       // [o][a] padded  17KB
    __shared__ int   list_s[NAT];          // compacted atom idx (2KB)
    __shared__ int   wcnt[17];

    const int t   = threadIdx.x;
    const int bin = blockIdx.x;
    const int b   = bin / NCLS;
    const int cls = bin % NCLS;

    // ---------------- prologue: independent loads in flight ----------------
    const int m0 = mapping[b * NAT + t];          // entries 0..255
    const int m1 = mapping[b * NAT + 256 + t];    // entries 256..511

    const float4* w0p = (const float4*)(W0 + (size_t)cls * IN0 * L0OUT);
    const float4* w1p = (const float4*)(W1 + (size_t)cls * HID * L0OUT);
    float4 w0r[2], w1r[4];
    #pragma unroll
    for (int r = 0; r < 2; r++) {
        int idx = r * NT + t;
        w0r[r] = __ldg(&w0p[(idx >> 4) * 64 + (idx & 15)]);
    }
    #pragma unroll
    for (int r = 0; r < 4; r++) {
        int idx = r * NT + t;
        w1r[r] = __ldg(&w1p[(idx >> 4) * 64 + (idx & 15)]);
    }

    // ---------------- deterministic compaction (index order) ---------------
    const int w    = t >> 5;
    const int lane = t & 31;
    const unsigned lmask = (1u << lane) - 1u;
    unsigned mk0 = __ballot_sync(0xffffffffu, m0 == cls);
    unsigned mk1 = __ballot_sync(0xffffffffu, m1 == cls);
    if (lane == 0) { wcnt[w] = __popc(mk0); wcnt[8 + w] = __popc(mk1); }
    __syncthreads();
    if (t == 0) {
        int s = 0;
        #pragma unroll
        for (int i = 0; i < 16; i++) { int c = wcnt[i]; wcnt[i] = s; s += c; }
        wcnt[16] = s;
    }
    __syncthreads();
    const int cnt = wcnt[16];
    if (m0 == cls) list_s[wcnt[w]     + __popc(mk0 & lmask)] = t;
    if (m1 == cls) list_s[wcnt[8 + w] + __popc(mk1 & lmask)] = 256 + t;

    // ---- stage dup'd weights: WaD[k][2o] = WaD[k][2o+1] = w0[k][o] ----
    #pragma unroll
    for (int r = 0; r < 2; r++) {
        int idx = r * NT + t, k = idx >> 4, c = idx & 15;
        float4 v = w0r[r];
        float* dst = &WaD[k * 128 + 8 * c];
        *(float4*)(dst)     = make_float4(v.x, v.x, v.y, v.y);
        *(float4*)(dst + 4) = make_float4(v.z, v.z, v.w, v.w);
    }
    #pragma unroll
    for (int r = 0; r < 4; r++) {
        int idx = r * NT + t, k = idx >> 4, c = idx & 15;
        float4 v = w1r[r];
        float* dst = &WbD[k * 128 + 8 * c];
        *(float4*)(dst)     = make_float4(v.x, v.x, v.y, v.y);
        *(float4*)(dst + 4) = make_float4(v.z, v.z, v.w, v.w);
    }
    __syncthreads();                       // list_s + weights visible

    // micro-tile: 8 atoms (4 f32x2 pairs) x 2 outputs per thread
    const int ag = t & 7;                  // atom group: a0 = 8*ag
    const int og = t >> 3;                 // output pair: o = 2*og, 2*og+1
    const int a0 = ag << 3;
    const float RS32 = 0.17677669529663687f;   // 1/sqrt(32)
    float part[2] = {0.f, 0.f};

    for (int start = 0; start < cnt; start += ATILE) {
        // ---- gather up to 64 atoms' first-32 features, transposed [k][a] --
        {
            int a = t >> 2, q = t & 3;     // atom slot, feature octet
            int i = start + a;
            float4 r0, r1;
            if (i < cnt) {
                int id = b * NAT + list_s[i];
                const float4* ap = (const float4*)(af + (size_t)id * DIN + q * 8);
                r0 = __ldg(&ap[0]);
                r1 = __ldg(&ap[1]);
            } else {
                r0 = make_float4(0.f, 0.f, 0.f, 0.f);
                r1 = r0;
            }
            int kb = q * 8;
            xs[(kb + 0) * ATILE + a] = r0.x;
            xs[(kb + 1) * ATILE + a] = r0.y;
            xs[(kb + 2) * ATILE + a] = r0.z;
            xs[(kb + 3) * ATILE + a] = r0.w;
            xs[(kb + 4) * ATILE + a] = r1.x;
            xs[(kb + 5) * ATILE + a] = r1.y;
            xs[(kb + 6) * ATILE + a] = r1.z;
            xs[(kb + 7) * ATILE + a] = r1.w;
        }
        __syncthreads();

        // ---- stage 1: [64a x 32k x 64o], a-paired FFMA2 (no packs) ----
        unsigned long long acc1[4][2] = {};
        #pragma unroll
        for (int k = 0; k < IN0; k++) {
            ulonglong2 xA = *(const ulonglong2*)&xs[k * ATILE + a0];
            ulonglong2 xB = *(const ulonglong2*)&xs[k * ATILE + a0 + 4];
            ulonglong2 wv = *(const ulonglong2*)&WaD[k * 128 + og * 4];
            unsigned long long xp[4] = {xA.x, xA.y, xB.x, xB.y};
            #pragma unroll
            for (int p = 0; p < 4; p++) {
                ffma2(acc1[p][0], xp[p], wv.x);
                ffma2(acc1[p][1], xp[p], wv.y);
            }
        }
        // silu + transposed store: rows o=2og+j, atoms a0..a0+7 (2 STS.128)
        #pragma unroll
        for (int j = 0; j < 2; j++) {
            float4 v0, v1;
            v0.x = silu_f(lo32(acc1[0][j]) * RS32);
            v0.y = silu_f(hi32(acc1[0][j]) * RS32);
            v0.z = silu_f(lo32(acc1[1][j]) * RS32);
            v0.w = silu_f(hi32(acc1[1][j]) * RS32);
            v1.x = silu_f(lo32(acc1[2][j]) * RS32);
            v1.y = silu_f(hi32(acc1[2][j]) * RS32);
            v1.z = silu_f(lo32(acc1[3][j]) * RS32);
            v1.w = silu_f(hi32(acc1[3][j]) * RS32);
            *(float4*)&s1[(2 * og + j) * PADA + a0]     = v0;
            *(float4*)&s1[(2 * og + j) * PADA + a0 + 4] = v1;
        }
        __syncthreads();

        // ---- stage 2: [64a x 64k x 64o]; pads are exact zeros ----
        unsigned long long acc2[4][2] = {};
        #pragma unroll
        for (int k = 0; k < HID; k++) {
            ulonglong2 xA = *(const ulonglong2*)&s1[k * PADA + a0];
            ulonglong2 xB = *(const ulonglong2*)&s1[k * PADA + a0 + 4];
            ulonglong2 wv = *(const ulonglong2*)&WbD[k * 128 + og * 4];
            unsigned long long xp[4] = {xA.x, xA.y, xB.x, xB.y};
            #pragma unroll
            for (int p = 0; p < 4; p++) {
                ffma2(acc2[p][0], xp[p], wv.x);
                ffma2(acc2[p][1], xp[p], wv.y);
            }
        }
        #pragma unroll
        for (int j = 0; j < 2; j++)
            #pragma unroll
            for (int p = 0; p < 4; p++)
                part[j] += silu_f(lo32(acc2[p][j]) * 0.125f)
                         + silu_f(hi32(acc2[p][j]) * 0.125f);
        __syncthreads();   // xs/s1 reused next tile
    }

    // ===== reduce part[] over the 8 atom-groups (warp lane bits 0-2) =====
    #pragma unroll
    for (int off = 1; off < 8; off <<= 1)
        #pragma unroll
        for (int j = 0; j < 2; j++)
            part[j] += __shfl_xor_sync(0xffffffffu, part[j], off);

    float* red = xs;               // alias: xs dead now (64 floats)
    if (ag == 0) {
        red[2 * og]     = part[0];
        red[2 * og + 1] = part[1];
    }
    __syncthreads();

    // ===== epilogue: out[b, cls*128 + o] = (red @ Wout[cls])[o] / 8 =====
    // split the 64-dot across two thread-halves to shorten the LDG chain
    float* psum = s1;              // alias: s1 dead (256 floats needed)
    {
        int o    = t & 127;
        int half = t >> 7;         // 0 or 1
        const float* wp = Wo + (size_t)cls * HID * NOUT + half * 32 * NOUT + o;
        float s = 0.0f;
        #pragma unroll
        for (int h = 0; h < 32; h++)
            s += red[half * 32 + h] * __ldg(&wp[h * NOUT]);
        psum[half * NOUT + o] = s;
    }
    __syncthreads();
    if (t < NOUT)
        out[b * (NCLS * NOUT) + cls * NOUT + t] =
            0.125f * (psum[t] + psum[NOUT + t]);
}

// ---------------------------------------------------------------------------
extern "C" void kernel_launch(void* const* d_in, const int* in_sizes, int n_in,
                              void* d_out, int out_size) {
    const float* af      = (const float*)d_in[0];   // atom_features
    const float* W0      = (const float*)d_in[1];   // W0_0
    const float* W1      = (const float*)d_in[5];   // W1_0
    const float* Wo      = (const float*)d_in[9];   // Wout
    const int*   mapping = (const int*)  d_in[10];  // mlp_mapping
    float* out = (float*)d_out;

    fused_kernel<<<NBINS, NT>>>(af, W0, W1, Wo, mapping, out);
}

// round 13
// speedup vs baseline: 1.3220x; 1.3220x over previous
#include <cuda_runtime.h>
#include <cstdint>

#define NCLS   10
#define NB     32
#define NBINS  (NB * NCLS)      // 320
#define NAT    512
#define DIN    272
#define HID    64
#define NOUT   128
#define L0OUT  256
#define IN0    32
#define ATILE  64
#define NT     128
#define PADA   68               // s1 row stride (floats): 16B multiple

__device__ __forceinline__ float silu_f(float x) {
    return x * (1.0f / (1.0f + __expf(-x)));
}

// packed dual-fp32 FMA: d.lo += a.lo*b.lo ; d.hi += a.hi*b.hi
__device__ __forceinline__ void ffma2(unsigned long long& d,
                                      unsigned long long a,
                                      unsigned long long b) {
    asm("fma.rn.f32x2 %0, %1, %2, %0;" : "+l"(d) : "l"(a), "l"(b));
}
__device__ __forceinline__ unsigned long long pack2(float x) {
    unsigned long long r;
    asm("mov.b64 %0, {%1, %1};" : "=l"(r) : "f"(x));
    return r;
}
__device__ __forceinline__ float lo32(unsigned long long v) {
    return __uint_as_float((unsigned)(v & 0xffffffffull));
}
__device__ __forceinline__ float hi32(unsigned long long v) {
    return __uint_as_float((unsigned)(v >> 32));
}

// ===========================================================================
// Single fused kernel: block = (b, cls), 128 threads, 4 CTAs/SM.
// Local compaction; 2-stage MLP on 64-atom tiles; o-paired FFMA2 with
// NATURAL weight layout (adjacent outputs form the f32x2 pair — no smem
// duplication, 3 LDS.128 per 32 MACs); sum s2 over atoms; apply Wout.
// ===========================================================================
__global__ __launch_bounds__(NT, 4) void fused_kernel(
    const float* __restrict__ af,      // (16384, 272)
    const float* __restrict__ W0,      // (T, 32, 256)
    const float* __restrict__ W1,      // (T, 64, 256)
    const float* __restrict__ Wo,      // (T, 64, 128)
    const int*   __restrict__ mapping, // (16384)
    float*       __restrict__ out)     // (NB, T*128)
{
    __shared__ float WaN[IN0 * HID];       // [k][o] natural   8KB
    __shared__ float WbN[HID * HID];       // [k][o] natural  16KB
    __shared__ float xs[IN0 * ATILE];      // [k][a]           8KB
    __shared__ float s1[HID * PADA];       // [o][a] padded   17KB
    __shared__ int   list_s[NAT];          // compacted atom idx (2KB)
    __shared__ int   wcnt[17];

    const int t   = threadIdx.x;
    const int bin = blockIdx.x;
    const int b   = bin / NCLS;
    const int cls = bin % NCLS;

    // ---------------- prologue: independent loads in flight ----------------
    int m[4];
    #pragma unroll
    for (int c = 0; c < 4; c++)
        m[c] = mapping[b * NAT + c * NT + t];

    const float4* w0p = (const float4*)(W0 + (size_t)cls * IN0 * L0OUT);
    const float4* w1p = (const float4*)(W1 + (size_t)cls * HID * L0OUT);
    float4 w0r[4], w1r[8];
    #pragma unroll
    for (int r = 0; r < 4; r++) {          // 512 float4s (live 64 cols)
        int idx = r * NT + t;
        w0r[r] = __ldg(&w0p[(idx >> 4) * 64 + (idx & 15)]);
    }
    #pragma unroll
    for (int r = 0; r < 8; r++) {          // 1024 float4s
        int idx = r * NT + t;
        w1r[r] = __ldg(&w1p[(idx >> 4) * 64 + (idx & 15)]);
    }

    // -------- deterministic compaction (ascending atom index order) --------
    const int w    = t >> 5;               // warp 0..3
    const int lane = t & 31;
    const unsigned lmask = (1u << lane) - 1u;
    unsigned mk[4];
    #pragma unroll
    for (int c = 0; c < 4; c++) {
        mk[c] = __ballot_sync(0xffffffffu, m[c] == cls);
        if (lane == 0) wcnt[c * 4 + w] = __popc(mk[c]);
    }
    __syncthreads();
    if (t == 0) {
        int s = 0;
        #pragma unroll
        for (int i = 0; i < 16; i++) { int c = wcnt[i]; wcnt[i] = s; s += c; }
        wcnt[16] = s;
    }
    __syncthreads();
    const int cnt = wcnt[16];
    #pragma unroll
    for (int c = 0; c < 4; c++)
        if (m[c] == cls)
            list_s[wcnt[c * 4 + w] + __popc(mk[c] & lmask)] = c * NT + t;

    // ---- stage natural weights ----
    #pragma unroll
    for (int r = 0; r < 4; r++) {
        int idx = r * NT + t;
        ((float4*)WaN)[(idx >> 4) * 16 + (idx & 15)] = w0r[r];
    }
    #pragma unroll
    for (int r = 0; r < 8; r++) {
        int idx = r * NT + t;
        ((float4*)WbN)[(idx >> 4) * 16 + (idx & 15)] = w1r[r];
    }
    __syncthreads();                       // list_s + weights visible

    // micro-tile: 8 atoms x 4 outputs (2 natural o-pairs) per thread
    const int ag = t & 7;                  // atom group: a0 = 8*ag
    const int og = t >> 3;                 // output quad: o0 = 4*og (0..60)
    const int a0 = ag << 3;
    const int o0 = og << 2;
    const float RS32 = 0.17677669529663687f;   // 1/sqrt(32)
    float part[4] = {0.f, 0.f, 0.f, 0.f};

    for (int start = 0; start < cnt; start += ATILE) {
        // ---- gather 64 atoms' first-32 features, transposed [k][a] ----
        {
            int a = t >> 1, h = t & 1;     // atom slot, feature half (16 f)
            int i = start + a;
            float4 r4[4];
            if (i < cnt) {
                int id = b * NAT + list_s[i];
                const float4* ap =
                    (const float4*)(af + (size_t)id * DIN + h * 16);
                #pragma unroll
                for (int j = 0; j < 4; j++) r4[j] = __ldg(&ap[j]);
            } else {
                #pragma unroll
                for (int j = 0; j < 4; j++)
                    r4[j] = make_float4(0.f, 0.f, 0.f, 0.f);
            }
            int kb = h * 16;
            #pragma unroll
            for (int j = 0; j < 4; j++) {
                xs[(kb + 4 * j + 0) * ATILE + a] = r4[j].x;
                xs[(kb + 4 * j + 1) * ATILE + a] = r4[j].y;
                xs[(kb + 4 * j + 2) * ATILE + a] = r4[j].z;
                xs[(kb + 4 * j + 3) * ATILE + a] = r4[j].w;
            }
        }
        __syncthreads();

        unsigned long long acc[8][2];

        // ---- stage 1: [64a x 32k x 64o] ----
        #pragma unroll
        for (int p = 0; p < 8; p++) { acc[p][0] = 0ull; acc[p][1] = 0ull; }
        #pragma unroll
        for (int k = 0; k < IN0; k++) {
            float4 xa = *(const float4*)&xs[k * ATILE + a0];
            float4 xb = *(const float4*)&xs[k * ATILE + a0 + 4];
            ulonglong2 wv = *(const ulonglong2*)&WaN[k * HID + o0];
            unsigned long long xd[8] = {
                pack2(xa.x), pack2(xa.y), pack2(xa.z), pack2(xa.w),
                pack2(xb.x), pack2(xb.y), pack2(xb.z), pack2(xb.w)};
            #pragma unroll
            for (int p = 0; p < 8; p++) {
                ffma2(acc[p][0], xd[p], wv.x);   // outputs o0, o0+1
                ffma2(acc[p][1], xd[p], wv.y);   // outputs o0+2, o0+3
            }
        }
        // silu + transposed store: 4 o-rows x 8 atoms (2 STS.128 per row)
        #pragma unroll
        for (int j = 0; j < 4; j++) {
            int pr = j >> 1, hi = j & 1;
            float4 v0, v1;
            v0.x = silu_f((hi ? hi32(acc[0][pr]) : lo32(acc[0][pr])) * RS32);
            v0.y = silu_f((hi ? hi32(acc[1][pr]) : lo32(acc[1][pr])) * RS32);
            v0.z = silu_f((hi ? hi32(acc[2][pr]) : lo32(acc[2][pr])) * RS32);
            v0.w = silu_f((hi ? hi32(acc[3][pr]) : lo32(acc[3][pr])) * RS32);
            v1.x = silu_f((hi ? hi32(acc[4][pr]) : lo32(acc[4][pr])) * RS32);
            v1.y = silu_f((hi ? hi32(acc[5][pr]) : lo32(acc[5][pr])) * RS32);
            v1.z = silu_f((hi ? hi32(acc[6][pr]) : lo32(acc[6][pr])) * RS32);
            v1.w = silu_f((hi ? hi32(acc[7][pr]) : lo32(acc[7][pr])) * RS32);
            *(float4*)&s1[(o0 + j) * PADA + a0]     = v0;
            *(float4*)&s1[(o0 + j) * PADA + a0 + 4] = v1;
        }
        __syncthreads();

        // ---- stage 2: [64a x 64k x 64o]; pads are exact zeros ----
        #pragma unroll
        for (int p = 0; p < 8; p++) { acc[p][0] = 0ull; acc[p][1] = 0ull; }
        #pragma unroll
        for (int k = 0; k < HID; k++) {
            float4 xa = *(const float4*)&s1[k * PADA + a0];
            float4 xb = *(const float4*)&s1[k * PADA + a0 + 4];
            ulonglong2 wv = *(const ulonglong2*)&WbN[k * HID + o0];
            unsigned long long xd[8] = {
                pack2(xa.x), pack2(xa.y), pack2(xa.z), pack2(xa.w),
                pack2(xb.x), pack2(xb.y), pack2(xb.z), pack2(xb.w)};
            #pragma unroll
            for (int p = 0; p < 8; p++) {
                ffma2(acc[p][0], xd[p], wv.x);
                ffma2(acc[p][1], xd[p], wv.y);
            }
        }
        #pragma unroll
        for (int p = 0; p < 8; p++) {
            part[0] += silu_f(lo32(acc[p][0]) * 0.125f);
            part[1] += silu_f(hi32(acc[p][0]) * 0.125f);
            part[2] += silu_f(lo32(acc[p][1]) * 0.125f);
            part[3] += silu_f(hi32(acc[p][1]) * 0.125f);
        }
        __syncthreads();   // xs/s1 reused next tile
    }

    // ===== reduce part[] over the 8 atom-groups (warp lane bits 0-2) =====
    #pragma unroll
    for (int off = 1; off < 8; off <<= 1)
        #pragma unroll
        for (int j = 0; j < 4; j++)
            part[j] += __shfl_xor_sync(0xffffffffu, part[j], off);

    float* red = xs;               // alias: xs dead now (need 64 floats)
    if (ag == 0) {
        #pragma unroll
        for (int j = 0; j < 4; j++) red[o0 + j] = part[j];
    }
    __syncthreads();

    // ===== epilogue: out[b, cls*128 + t] = (red @ Wout[cls])[t] / 8 =====
    {
        const float* wp = Wo + (size_t)cls * HID * NOUT + t;
        float s = 0.0f;
        #pragma unroll
        for (int h = 0; h < HID; h++)
            s += red[h] * __ldg(&wp[h * NOUT]);
        out[b * (NCLS * NOUT) + cls * NOUT + t] = 0.125f * s;
    }
}

// ---------------------------------------------------------------------------
extern "C" void kernel_launch(void* const* d_in, const int* in_sizes, int n_in,
                              void* d_out, int out_size) {
    const float* af      = (const float*)d_in[0];   // atom_features
    const float* W0      = (const float*)d_in[1];   // W0_0
    const float* W1      = (const float*)d_in[5];   // W1_0
    const float* Wo      = (const float*)d_in[9];   // Wout
    const int*   mapping = (const int*)  d_in[10];  // mlp_mapping
    float* out = (float*)d_out;

    fused_kernel<<<NBINS, NT>>>(af, W0, W1, Wo, mapping, out);
}

// round 14
// speedup vs baseline: 1.7508x; 1.3244x over previous
#include <cuda_runtime.h>
#include <cstdint>

#define NCLS   10
#define NB     32
#define NBINS  (NB * NCLS)      // 320
#define NAT    512
#define DIN    272
#define HID    64
#define NOUT   128
#define L0OUT  256
#define IN0    32
#define NT     256
#define SWPAD  12               // sw row stride (floats), 48B = 16B multiple

__device__ __forceinline__ float silu_f(float x) {
    return x * (1.0f / (1.0f + __expf(-x)));
}

// packed dual-fp32 FMA: d.lo += a.lo*b.lo ; d.hi += a.hi*b.hi
__device__ __forceinline__ void ffma2(unsigned long long& d,
                                      unsigned long long a,
                                      unsigned long long b) {
    asm("fma.rn.f32x2 %0, %1, %2, %0;" : "+l"(d) : "l"(a), "l"(b));
}
__device__ __forceinline__ unsigned long long pack2(float x) {
    unsigned long long r;
    asm("mov.b64 %0, {%1, %1};" : "=l"(r) : "f"(x));
    return r;
}
__device__ __forceinline__ float lo32(unsigned long long v) {
    return __uint_as_float((unsigned)(v & 0xffffffffull));
}
__device__ __forceinline__ float hi32(unsigned long long v) {
    return __uint_as_float((unsigned)(v >> 32));
}

// ===========================================================================
// Warp-autonomous fused kernel. Block = (b, cls), 8 warps.
// After one barrier (weights + compaction), each warp independently processes
// 8-atom groups in warp-private smem slices with only __syncwarp ordering.
// One final barrier merges warp partials; Wout epilogue writes 128 outputs.
// Stateless: no global scratch, no atomics.
// ===========================================================================
__global__ __launch_bounds__(NT, 2) void fused_kernel(
    const float* __restrict__ af,      // (16384, 272)
    const float* __restrict__ W0,      // (T, 32, 256)
    const float* __restrict__ W1,      // (T, 64, 256)
    const float* __restrict__ Wo,      // (T, 64, 128)
    const int*   __restrict__ mapping, // (16384)
    float*       __restrict__ out)     // (NB, T*128)
{
    __shared__ float WaN[IN0 * HID];        // [k][o] natural       8KB
    __shared__ float WbN[HID * HID];        // [k][o] natural      16KB
    __shared__ float xw[8][IN0 * 8];        // per-warp x  [k][a]   8KB
    __shared__ float sw[8][HID * SWPAD];    // per-warp s1 [o-row]  24KB
    __shared__ float pw[8 * HID];           // warp partials        2KB
    __shared__ float red[HID];              // merged sum of s2
    __shared__ int   list_s[NAT];           // compacted atom idx   2KB
    __shared__ int   wcnt[17];

    const int t    = threadIdx.x;
    const int w    = t >> 5;
    const int lane = t & 31;
    const int bin  = blockIdx.x;
    const int b    = bin / NCLS;
    const int cls  = bin % NCLS;

    // ---------------- prologue: independent loads in flight ----------------
    const int m0 = mapping[b * NAT + t];
    const int m1 = mapping[b * NAT + 256 + t];

    const float4* w0p = (const float4*)(W0 + (size_t)cls * IN0 * L0OUT);
    const float4* w1p = (const float4*)(W1 + (size_t)cls * HID * L0OUT);
    float4 w0r[2], w1r[4];
    #pragma unroll
    for (int r = 0; r < 2; r++) {
        int idx = r * NT + t;
        w0r[r] = __ldg(&w0p[(idx >> 4) * 64 + (idx & 15)]);
    }
    #pragma unroll
    for (int r = 0; r < 4; r++) {
        int idx = r * NT + t;
        w1r[r] = __ldg(&w1p[(idx >> 4) * 64 + (idx & 15)]);
    }

    // -------- deterministic compaction (ascending atom index order) --------
    const unsigned lmask = (1u << lane) - 1u;
    unsigned mk0 = __ballot_sync(0xffffffffu, m0 == cls);
    unsigned mk1 = __ballot_sync(0xffffffffu, m1 == cls);
    if (lane == 0) { wcnt[w] = __popc(mk0); wcnt[8 + w] = __popc(mk1); }
    __syncthreads();
    if (t == 0) {
        int s = 0;
        #pragma unroll
        for (int i = 0; i < 16; i++) { int c = wcnt[i]; wcnt[i] = s; s += c; }
        wcnt[16] = s;
    }
    __syncthreads();
    const int cnt = wcnt[16];
    if (m0 == cls) list_s[wcnt[w]     + __popc(mk0 & lmask)] = t;
    if (m1 == cls) list_s[wcnt[8 + w] + __popc(mk1 & lmask)] = 256 + t;

    // ---- stage natural weights ----
    #pragma unroll
    for (int r = 0; r < 2; r++) {
        int idx = r * NT + t;
        ((float4*)WaN)[(idx >> 4) * 16 + (idx & 15)] = w0r[r];
    }
    #pragma unroll
    for (int r = 0; r < 4; r++) {
        int idx = r * NT + t;
        ((float4*)WbN)[(idx >> 4) * 16 + (idx & 15)] = w1r[r];
    }
    __syncthreads();        // the ONLY pre-mainloop block barrier

    // =================== warp-autonomous mainloop ===========================
    // lane owns outputs (2*lane, 2*lane+1); 8 atoms per group as 4 f32x2 pairs
    const int ngroups = (cnt + 7) >> 3;
    const float RS32 = 0.17677669529663687f;   // 1/sqrt(32)
    float part0 = 0.f, part1 = 0.f;
    float* xwm = xw[w];
    float* swm = sw[w];

    for (int g = w; g < ngroups; g += 8) {
        // ---- gather 8 atoms' first-32 features into xw[w] ([k][a]) ----
        {
            int a = lane & 7;              // atom slot
            int h = lane >> 3;             // feature-eighth pair (8 floats)
            int i = g * 8 + a;
            float4 r0, r1;
            if (i < cnt) {
                int id = b * NAT + list_s[i];
                const float4* ap = (const float4*)(af + (size_t)id * DIN + h * 8);
                r0 = __ldg(&ap[0]);
                r1 = __ldg(&ap[1]);
            } else {
                r0 = make_float4(0.f, 0.f, 0.f, 0.f);
                r1 = r0;
            }
            int kb = h * 8;
            xwm[(kb + 0) * 8 + a] = r0.x;
            xwm[(kb + 1) * 8 + a] = r0.y;
            xwm[(kb + 2) * 8 + a] = r0.z;
            xwm[(kb + 3) * 8 + a] = r0.w;
            xwm[(kb + 4) * 8 + a] = r1.x;
            xwm[(kb + 5) * 8 + a] = r1.y;
            xwm[(kb + 6) * 8 + a] = r1.z;
            xwm[(kb + 7) * 8 + a] = r1.w;
        }
        __syncwarp();

        // ---- stage 1: [8a x 32k x 64o], atom-paired FFMA2 ----
        unsigned long long acc[2][4];
        #pragma unroll
        for (int j = 0; j < 2; j++)
            #pragma unroll
            for (int p = 0; p < 4; p++) acc[j][p] = 0ull;
        #pragma unroll
        for (int k = 0; k < IN0; k++) {
            ulonglong2 u0 = *(const ulonglong2*)&xwm[k * 8];      // broadcast
            ulonglong2 u1 = *(const ulonglong2*)&xwm[k * 8 + 4];
            float2 wf = *(const float2*)&WaN[k * HID + 2 * lane];
            unsigned long long wd0 = pack2(wf.x), wd1 = pack2(wf.y);
            unsigned long long xp[4] = {u0.x, u0.y, u1.x, u1.y};
            #pragma unroll
            for (int p = 0; p < 4; p++) {
                ffma2(acc[0][p], xp[p], wd0);
                ffma2(acc[1][p], xp[p], wd1);
            }
        }
        // silu + store s1 rows (o = 2*lane + j), 8 atoms each (2 STS.128)
        #pragma unroll
        for (int j = 0; j < 2; j++) {
            float4 v0, v1;
            v0.x = silu_f(lo32(acc[j][0]) * RS32);
            v0.y = silu_f(hi32(acc[j][0]) * RS32);
            v0.z = silu_f(lo32(acc[j][1]) * RS32);
            v0.w = silu_f(hi32(acc[j][1]) * RS32);
            v1.x = silu_f(lo32(acc[j][2]) * RS32);
            v1.y = silu_f(hi32(acc[j][2]) * RS32);
            v1.z = silu_f(lo32(acc[j][3]) * RS32);
            v1.w = silu_f(hi32(acc[j][3]) * RS32);
            *(float4*)&swm[(2 * lane + j) * SWPAD]     = v0;
            *(float4*)&swm[(2 * lane + j) * SWPAD + 4] = v1;
        }
        __syncwarp();

        // ---- stage 2: [8a x 64k x 64o]; pad atoms are exact zeros ----
        unsigned long long acc2[2][4];
        #pragma unroll
        for (int j = 0; j < 2; j++)
            #pragma unroll
            for (int p = 0; p < 4; p++) acc2[j][p] = 0ull;
        #pragma unroll
        for (int k = 0; k < HID; k++) {
            ulonglong2 u0 = *(const ulonglong2*)&swm[k * SWPAD];  // broadcast
            ulonglong2 u1 = *(const ulonglong2*)&swm[k * SWPAD + 4];
            float2 wf = *(const float2*)&WbN[k * HID + 2 * lane];
            unsigned long long wd0 = pack2(wf.x), wd1 = pack2(wf.y);
            unsigned long long xp[4] = {u0.x, u0.y, u1.x, u1.y};
            #pragma unroll
            for (int p = 0; p < 4; p++) {
                ffma2(acc2[0][p], xp[p], wd0);
                ffma2(acc2[1][p], xp[p], wd1);
            }
        }
        #pragma unroll
        for (int p = 0; p < 4; p++) {
            part0 += silu_f(lo32(acc2[0][p]) * 0.125f)
                   + silu_f(hi32(acc2[0][p]) * 0.125f);
            part1 += silu_f(lo32(acc2[1][p]) * 0.125f)
                   + silu_f(hi32(acc2[1][p]) * 0.125f);
        }
        __syncwarp();      // xw/sw reused next group
    }

    // ---- merge warp partials (inactive warps contribute zeros) ----
    pw[w * HID + 2 * lane]     = part0;
    pw[w * HID + 2 * lane + 1] = part1;
    __syncthreads();
    if (t < HID) {
        float s = 0.f;
        #pragma unroll
        for (int j = 0; j < 8; j++) s += pw[j * HID + t];
        red[t] = s;
    }
    __syncthreads();

    // ===== epilogue: out[b, cls*128 + o] = (red @ Wout[cls])[o] / 8 =====
    if (t < NOUT) {
        const float* wp = Wo + (size_t)cls * HID * NOUT + t;
        float s = 0.0f;
        #pragma unroll
        for (int h = 0; h < HID; h++)
            s += red[h] * __ldg(&wp[h * NOUT]);
        out[b * (NCLS * NOUT) + cls * NOUT + t] = 0.125f * s;
    }
}

// ---------------------------------------------------------------------------
extern "C" void kernel_launch(void* const* d_in, const int* in_sizes, int n_in,
                              void* d_out, int out_size) {
    const float* af      = (const float*)d_in[0];   // atom_features
    const float* W0      = (const float*)d_in[1];   // W0_0
    const float* W1      = (const float*)d_in[5];   // W1_0
    const float* Wo      = (const float*)d_in[9];   // Wout
    const int*   mapping = (const int*)  d_in[10];  // mlp_mapping
    float* out = (float*)d_out;

    fused_kernel<<<NBINS, NT>>>(af, W0, W1, Wo, mapping, out);
}

// round 15
// speedup vs baseline: 1.9570x; 1.1178x over previous
#include <cuda_runtime.h>
#include <cstdint>

#define NCLS   10
#define NB     32
#define NBINS  (NB * NCLS)      // 320
#define NAT    512
#define DIN    272
#define HID    64
#define NOUT   128
#define L0OUT  256
#define IN0    32
#define NT     256
#define SWPAD  12               // sw row stride (floats), 48B = 16B multiple

__device__ __forceinline__ float silu_f(float x) {
    return x * (1.0f / (1.0f + __expf(-x)));
}

// packed dual-fp32 FMA: d.lo += a.lo*b.lo ; d.hi += a.hi*b.hi
__device__ __forceinline__ void ffma2(unsigned long long& d,
                                      unsigned long long a,
                                      unsigned long long b) {
    asm("fma.rn.f32x2 %0, %1, %2, %0;" : "+l"(d) : "l"(a), "l"(b));
}
__device__ __forceinline__ unsigned long long pack2(float x) {
    unsigned long long r;
    asm("mov.b64 %0, {%1, %1};" : "=l"(r) : "f"(x));
    return r;
}
__device__ __forceinline__ float lo32(unsigned long long v) {
    return __uint_as_float((unsigned)(v & 0xffffffffull));
}
__device__ __forceinline__ float hi32(unsigned long long v) {
    return __uint_as_float((unsigned)(v >> 32));
}

// ===========================================================================
// Warp-autonomous fused kernel, 3 CTAs/SM (all 320 blocks co-resident).
// Block = (b, cls), 8 warps. After one barrier (weights + compaction), each
// warp independently processes 8-atom groups in warp-private smem slices
// with only __syncwarp ordering. Final barrier merges warp partials.
// Stateless: no global scratch, no atomics.
// ===========================================================================
__global__ __launch_bounds__(NT, 3) void fused_kernel(
    const float* __restrict__ af,      // (16384, 272)
    const float* __restrict__ W0,      // (T, 32, 256)
    const float* __restrict__ W1,      // (T, 64, 256)
    const float* __restrict__ Wo,      // (T, 64, 128)
    const int*   __restrict__ mapping, // (16384)
    float*       __restrict__ out)     // (NB, T*128)
{
    __shared__ float WaN[IN0 * HID];        // [k][o] natural       8KB
    __shared__ float WbN[HID * HID];        // [k][o] natural      16KB
    __shared__ float xw[8][IN0 * 8];        // per-warp x  [k][a]   8KB
    __shared__ float sw[8][HID * SWPAD];    // per-warp s1 [o-row] 24KB
    __shared__ float pw[8 * HID];           // warp partials        2KB
    __shared__ float red[HID];              // merged sum of s2
    __shared__ int   list_s[NAT];           // compacted atom idx   2KB
    __shared__ int   wcnt[17];

    const int t    = threadIdx.x;
    const int w    = t >> 5;
    const int lane = t & 31;
    const int bin  = blockIdx.x;
    const int b    = bin / NCLS;
    const int cls  = bin % NCLS;

    // ---------------- prologue: independent loads in flight ----------------
    const int m0 = mapping[b * NAT + t];
    const int m1 = mapping[b * NAT + 256 + t];

    const float4* w0p = (const float4*)(W0 + (size_t)cls * IN0 * L0OUT);
    const float4* w1p = (const float4*)(W1 + (size_t)cls * HID * L0OUT);
    float4 w0r[2], w1r[4];
    #pragma unroll
    for (int r = 0; r < 2; r++) {
        int idx = r * NT + t;
        w0r[r] = __ldg(&w0p[(idx >> 4) * 64 + (idx & 15)]);
    }
    #pragma unroll
    for (int r = 0; r < 4; r++) {
        int idx = r * NT + t;
        w1r[r] = __ldg(&w1p[(idx >> 4) * 64 + (idx & 15)]);
    }

    // -------- deterministic compaction (ascending atom index order) --------
    const unsigned lmask = (1u << lane) - 1u;
    unsigned mk0 = __ballot_sync(0xffffffffu, m0 == cls);
    unsigned mk1 = __ballot_sync(0xffffffffu, m1 == cls);
    if (lane == 0) { wcnt[w] = __popc(mk0); wcnt[8 + w] = __popc(mk1); }
    __syncthreads();
    if (t == 0) {
        int s = 0;
        #pragma unroll
        for (int i = 0; i < 16; i++) { int c = wcnt[i]; wcnt[i] = s; s += c; }
        wcnt[16] = s;
    }
    __syncthreads();
    const int cnt = wcnt[16];
    if (m0 == cls) list_s[wcnt[w]     + __popc(mk0 & lmask)] = t;
    if (m1 == cls) list_s[wcnt[8 + w] + __popc(mk1 & lmask)] = 256 + t;

    // ---- stage natural weights ----
    #pragma unroll
    for (int r = 0; r < 2; r++) {
        int idx = r * NT + t;
        ((float4*)WaN)[(idx >> 4) * 16 + (idx & 15)] = w0r[r];
    }
    #pragma unroll
    for (int r = 0; r < 4; r++) {
        int idx = r * NT + t;
        ((float4*)WbN)[(idx >> 4) * 16 + (idx & 15)] = w1r[r];
    }
    __syncthreads();        // the ONLY pre-mainloop block barrier

    // =================== warp-autonomous mainloop ===========================
    // lane owns outputs (2*lane, 2*lane+1); 8 atoms per group as 4 f32x2 pairs
    const int ngroups = (cnt + 7) >> 3;
    const float RS32 = 0.17677669529663687f;   // 1/sqrt(32)
    float part0 = 0.f, part1 = 0.f;
    float* xwm = xw[w];
    float* swm = sw[w];

    for (int g = w; g < ngroups; g += 8) {
        // ---- gather 8 atoms' first-32 features into xw[w] ([k][a]) ----
        {
            int a = lane & 7;              // atom slot
            int h = lane >> 3;             // feature-eighth pair (8 floats)
            int i = g * 8 + a;
            float4 r0, r1;
            if (i < cnt) {
                int id = b * NAT + list_s[i];
                const float4* ap = (const float4*)(af + (size_t)id * DIN + h * 8);
                r0 = __ldg(&ap[0]);
                r1 = __ldg(&ap[1]);
            } else {
                r0 = make_float4(0.f, 0.f, 0.f, 0.f);
                r1 = r0;
            }
            int kb = h * 8;
            xwm[(kb + 0) * 8 + a] = r0.x;
            xwm[(kb + 1) * 8 + a] = r0.y;
            xwm[(kb + 2) * 8 + a] = r0.z;
            xwm[(kb + 3) * 8 + a] = r0.w;
            xwm[(kb + 4) * 8 + a] = r1.x;
            xwm[(kb + 5) * 8 + a] = r1.y;
            xwm[(kb + 6) * 8 + a] = r1.z;
            xwm[(kb + 7) * 8 + a] = r1.w;
        }
        __syncwarp();

        // ---- stage 1: [8a x 32k x 64o], atom-paired FFMA2 ----
        unsigned long long acc[2][4];
        #pragma unroll
        for (int j = 0; j < 2; j++)
            #pragma unroll
            for (int p = 0; p < 4; p++) acc[j][p] = 0ull;
        #pragma unroll
        for (int k = 0; k < IN0; k++) {
            ulonglong2 u0 = *(const ulonglong2*)&xwm[k * 8];      // broadcast
            ulonglong2 u1 = *(const ulonglong2*)&xwm[k * 8 + 4];
            float2 wf = *(const float2*)&WaN[k * HID + 2 * lane];
            unsigned long long wd0 = pack2(wf.x), wd1 = pack2(wf.y);
            unsigned long long xp[4] = {u0.x, u0.y, u1.x, u1.y};
            #pragma unroll
            for (int p = 0; p < 4; p++) {
                ffma2(acc[0][p], xp[p], wd0);
                ffma2(acc[1][p], xp[p], wd1);
            }
        }
        // silu + store s1 rows (o = 2*lane + j), 8 atoms each (2 STS.128)
        #pragma unroll
        for (int j = 0; j < 2; j++) {
            float4 v0, v1;
            v0.x = silu_f(lo32(acc[j][0]) * RS32);
            v0.y = silu_f(hi32(acc[j][0]) * RS32);
            v0.z = silu_f(lo32(acc[j][1]) * RS32);
            v0.w = silu_f(hi32(acc[j][1]) * RS32);
            v1.x = silu_f(lo32(acc[j][2]) * RS32);
            v1.y = silu_f(hi32(acc[j][2]) * RS32);
            v1.z = silu_f(lo32(acc[j][3]) * RS32);
            v1.w = silu_f(hi32(acc[j][3]) * RS32);
            *(float4*)&swm[(2 * lane + j) * SWPAD]     = v0;
            *(float4*)&swm[(2 * lane + j) * SWPAD + 4] = v1;
        }
        __syncwarp();

        // ---- stage 2: [8a x 64k x 64o]; pad atoms are exact zeros ----
        unsigned long long acc2[2][4];
        #pragma unroll
        for (int j = 0; j < 2; j++)
            #pragma unroll
            for (int p = 0; p < 4; p++) acc2[j][p] = 0ull;
        #pragma unroll
        for (int k = 0; k < HID; k++) {
            ulonglong2 u0 = *(const ulonglong2*)&swm[k * SWPAD];  // broadcast
            ulonglong2 u1 = *(const ulonglong2*)&swm[k * SWPAD + 4];
            float2 wf = *(const float2*)&WbN[k * HID + 2 * lane];
            unsigned long long wd0 = pack2(wf.x), wd1 = pack2(wf.y);
            unsigned long long xp[4] = {u0.x, u0.y, u1.x, u1.y};
            #pragma unroll
            for (int p = 0; p < 4; p++) {
                ffma2(acc2[0][p], xp[p], wd0);
                ffma2(acc2[1][p], xp[p], wd1);
            }
        }
        #pragma unroll
        for (int p = 0; p < 4; p++) {
            part0 += silu_f(lo32(acc2[0][p]) * 0.125f)
                   + silu_f(hi32(acc2[0][p]) * 0.125f);
            part1 += silu_f(lo32(acc2[1][p]) * 0.125f)
                   + silu_f(hi32(acc2[1][p]) * 0.125f);
        }
        __syncwarp();      // xw/sw reused next group
    }

    // ---- merge warp partials (inactive warps contribute zeros) ----
    pw[w * HID + 2 * lane]     = part0;
    pw[w * HID + 2 * lane + 1] = part1;
    __syncthreads();
    if (t < HID) {
        float s = 0.f;
        #pragma unroll
        for (int j = 0; j < 8; j++) s += pw[j * HID + t];
        red[t] = s;
    }
    __syncthreads();

    // ===== epilogue: out[b, cls*128 + o] = (red @ Wout[cls])[o] / 8 =====
    if (t < NOUT) {
        const float* wp = Wo + (size_t)cls * HID * NOUT + t;
        float s = 0.0f;
        #pragma unroll
        for (int h = 0; h < HID; h++)
            s += red[h] * __ldg(&wp[h * NOUT]);
        out[b * (NCLS * NOUT) + cls * NOUT + t] = 0.125f * s;
    }
}

// ---------------------------------------------------------------------------
extern "C" void kernel_launch(void* const* d_in, const int* in_sizes, int n_in,
                              void* d_out, int out_size) {
    const float* af      = (const float*)d_in[0];   // atom_features
    const float* W0      = (const float*)d_in[1];   // W0_0
    const float* W1      = (const float*)d_in[5];   // W1_0
    const float* Wo      = (const float*)d_in[9];   // Wout
    const int*   mapping = (const int*)  d_in[10];  // mlp_mapping
    float* out = (float*)d_out;

    fused_kernel<<<NBINS, NT>>>(af, W0, W1, Wo, mapping, out);
}